// round 11
// baseline (speedup 1.0000x reference)
#include <cuda_runtime.h>
#include <math.h>
#include <stdint.h>

#define BB   256   // batch
#define TT   512   // seq len
#define DD   64    // input size
#define HH   256   // hidden
#define G4H  1024  // 4*H

// ---------------- static device scratch (no runtime allocations) ----------------
__device__ float g_xw[(size_t)TT * BB * G4H];   // input projections (reused per layer)
__device__ float g_out0[(size_t)TT * BB * HH];  // layer-0 outputs
__device__ float g_hfin[BB * HH];               // final hidden state of layer 1

// packed f32x2 FMA (Blackwell FFMA2; PTX-only)
__device__ __forceinline__ void ffma2(double& acc, double a, double b) {
    asm("fma.rn.f32x2 %0, %1, %2, %3;" : "=d"(acc) : "d"(a), "d"(b), "d"(acc));
}
__device__ __forceinline__ float dsum(double d) {
    return __int_as_float(__double2loint(d)) + __int_as_float(__double2hiint(d));
}

// ---------------- input projection GEMM: 64x128 tiles, f32x2 ----------------
// g_xw[m][n] = sum_k in[m][k] * W[n][k] + b1[n] + b2[n],  m = t*BB + b
// SRC==0: in = x, layout [b][t][d].  SRC==1: in = g_out0, row m contiguous.
// 256 threads; thread = (nn = n-lane, mg = warp): 8 m-rows x 4 n-cols per thread.
#define PROJ_SMEM_BYTES ((64 * 66 + 128 * 66) * 4)   // 50,688 B (dynamic)
template<int K, int SRC>
__global__ __launch_bounds__(256)
void proj_kernel(const float* __restrict__ in,
                 const float* __restrict__ W,
                 const float* __restrict__ b1,
                 const float* __restrict__ b2)
{
    extern __shared__ __align__(16) float psm[];
    float* As = psm;               // [64][66]
    float* Wsm = psm + 64 * 66;    // [128][66]

    const int m0  = blockIdx.x * 64;
    const int n0  = blockIdx.y * 128;
    const int tid = threadIdx.x;        // 256 threads
    const int nn  = tid & 31;
    const int mg  = tid >> 5;           // 0..7 -> rows mg*8 .. mg*8+7

    double acc[8][4];
    #pragma unroll
    for (int i = 0; i < 8; i++)
        #pragma unroll
        for (int j = 0; j < 4; j++) acc[i][j] = 0.0;

    for (int k0 = 0; k0 < K; k0 += 64) {
        // stage A tile: 64 rows x 64 k (float2 granules)
        for (int idx = tid; idx < 64 * 32; idx += 256) {
            int r  = idx >> 5;
            int kd = idx & 31;
            int m  = m0 + r;
            const float* src;
            if (SRC == 0) {
                int b = m & (BB - 1);
                int t = m >> 8;
                src = in + (size_t)(b * TT + t) * DD;
            } else {
                src = g_out0 + (size_t)m * K;
            }
            *(float2*)&As[r * 66 + kd * 2] = *(const float2*)(src + k0 + kd * 2);
        }
        // stage W tile: 128 rows x 64 k
        for (int idx = tid; idx < 128 * 32; idx += 256) {
            int r  = idx >> 5;
            int kd = idx & 31;
            *(float2*)&Wsm[r * 66 + kd * 2] =
                *(const float2*)(W + (size_t)(n0 + r) * K + k0 + kd * 2);
        }
        __syncthreads();

        #pragma unroll 4
        for (int kk = 0; kk < 32; kk++) {
            double a[8], w[4];
            #pragma unroll
            for (int i = 0; i < 8; i++) a[i] = *(const double*)&As[(mg * 8 + i) * 66 + kk * 2];
            #pragma unroll
            for (int j = 0; j < 4; j++) w[j] = *(const double*)&Wsm[(nn + 32 * j) * 66 + kk * 2];
            #pragma unroll
            for (int i = 0; i < 8; i++)
                #pragma unroll
                for (int j = 0; j < 4; j++)
                    ffma2(acc[i][j], a[i], w[j]);
        }
        __syncthreads();
    }

    #pragma unroll
    for (int i = 0; i < 8; i++) {
        int m = m0 + mg * 8 + i;
        #pragma unroll
        for (int j = 0; j < 4; j++) {
            int n = n0 + nn + 32 * j;
            g_xw[(size_t)m * G4H + n] = dsum(acc[i][j]) + b1[n] + b2[n];
        }
    }
}

// ---------------- MUFU-based gates (cheap: cost is per-warp, not per-element) ----
__device__ __forceinline__ float sigmoid_mufu(float z) {
    return __fdividef(1.0f, 1.0f + __expf(-z));
}
__device__ __forceinline__ float tanh_mufu(float z) {
    // tanh(z) = 1 - 2/(exp(2z)+1); saturates correctly at +-inf
    return 1.0f - __fdividef(2.0f, __expf(2.0f * z) + 1.0f);
}

// ---------------- mbarrier helpers (cluster scope) ----------------
__device__ __forceinline__ void mbar_wait_cluster(uint32_t addr, uint32_t parity) {
    asm volatile(
        "{\n\t"
        ".reg .pred P;\n\t"
        "MW_%=:\n\t"
        "mbarrier.try_wait.parity.acquire.cluster.shared::cta.b64 P, [%0], %1, 0x989680;\n\t"
        "@!P bra MW_%=;\n\t"
        "}"
        :: "r"(addr), "r"(parity) : "memory");
}
__device__ __forceinline__ void mbar_arrive_remote(uint32_t remote_addr) {
    asm volatile(
        "mbarrier.arrive.release.cluster.shared::cluster.b64 _, [%0];"
        :: "r"(remote_addr) : "memory");
}

// ---------------- persistent cluster LSTM layer (512 thr, mbarrier sync) ----------
// Grid (8, 16): x = j-tile (cluster rank), y = b-tile.  16 warps / CTA.
// GEMM: warp = (kh k-half, bh batch-half, rb row-block); thread: 1 row x 8 b x 128 k.
// Partials via Zs[2][128][17]; epilogue thread = (j = lane, batch = warp).
// h exchange: DSMEM multicast stores + two phase-alternating mbarriers (count 128 =
// 8 CTAs x 16 warps, warp-elected arrive). No cluster gang barrier in the loop
// (no CCTL.IVALL). One __syncthreads per step for the Zs handoff.
#define WS_STRIDE 260
#define HS_STRIDE 264
#define ZS_STRIDE 17
#define WS_FLOATS (128 * WS_STRIDE)             // 33280
#define HS_FLOATS (2 * 16 * HS_STRIDE)          // 8448
#define ZS_FLOATS (2 * 128 * ZS_STRIDE)         // 4352
#define MB_DELTA  ((HS_FLOATS + ZS_FLOATS) * 4) // byte offset: Hs base -> mbarriers
#define LSTM_SMEM_BYTES ((WS_FLOATS + HS_FLOATS + ZS_FLOATS) * 4 + 16)  // 184,336 B

__global__ __cluster_dims__(8, 1, 1) __launch_bounds__(512, 1)
void lstm_layer_kernel(const float* __restrict__ Whh, int write_out0)
{
    extern __shared__ __align__(16) float smem[];
    float* Ws = smem;                          // [128][WS_STRIDE], row r = g*32+jj
    float* Hs = smem + WS_FLOATS;              // [2][16][HS_STRIDE]
    float* Zs = smem + WS_FLOATS + HS_FLOATS;  // [2][128][ZS_STRIDE]

    const int tid  = threadIdx.x;              // 512 threads
    const int lane = tid & 31;
    const int warp = tid >> 5;                 // 0..15
    // GEMM mapping
    const int kh    = warp & 1;
    const int bh    = (warp >> 1) & 1;
    const int rb    = warp >> 2;
    const int r     = rb * 32 + lane;          // row = gate*32 + j
    const int kbase = kh * 128;
    const int bbase = bh * 8;
    // epilogue mapping
    const int cg = lane;
    const int bq = warp;
    const int by = blockIdx.x;                 // cluster rank (j-tile)
    const int bx = blockIdx.y;                 // b-tile
    const int j0 = by * 32;
    const int jg = j0 + cg;
    const int b0 = bx * 16;

    // Stage Whh slice: smem row c = g*32+jj  <-  Whh row g*HH + j0 + jj
    for (int idx = tid; idx < 128 * 64; idx += 512) {
        int c   = idx >> 6;
        int kq  = idx & 63;
        int row = (c >> 5) * HH + j0 + (c & 31);
        float4 v = *(const float4*)(Whh + (size_t)row * HH + kq * 4);
        *(float4*)(Ws + c * WS_STRIDE + kq * 4) = v;
    }
    // Zero Hs buffer 0 (step 0 reads it; step 0's h goes to buffer 1)
    for (int idx = tid; idx < 16 * HS_STRIDE; idx += 512)
        Hs[idx] = 0.0f;

    // Local smem addresses
    uint32_t hs_local;
    asm("{ .reg .u64 t; cvta.to.shared.u64 t, %1; cvt.u32.u64 %0, t; }"
        : "=r"(hs_local) : "l"(Hs));
    const uint32_t mb_local = hs_local + MB_DELTA;   // two 8-byte mbarriers

    if (tid == 0) {
        asm volatile("mbarrier.init.shared.b64 [%0], %1;" :: "r"(mb_local),     "r"(128u));
        asm volatile("mbarrier.init.shared.b64 [%0], %1;" :: "r"(mb_local + 8), "r"(128u));
    }
    __syncthreads();

    // Remote Hs base addresses for all 8 cluster ranks (mbar = +MB_DELTA)
    uint32_t peer[8];
    #pragma unroll
    for (int p = 0; p < 8; p++)
        asm("mapa.shared::cluster.u32 %0, %1, %2;"
            : "=r"(peer[p]) : "r"(hs_local), "r"(p));

    // One-time cluster barrier: all mbarriers initialized before any remote arrive
    asm volatile("barrier.cluster.arrive.aligned;" ::: "memory");
    asm volatile("barrier.cluster.wait.aligned;"   ::: "memory");

    float creg = 0.0f;                               // c for (b0+bq, jg)
    const float* wrow = Ws + r * WS_STRIDE + kbase;

    for (int t = 0; t < TT; t++) {
        // Prefetch xw (independent of h; DRAM latency overlaps the wait+GEMM)
        const float* xw_b = g_xw + ((size_t)t * BB + (b0 + bq)) * G4H + jg;
        float xw0 = __ldg(xw_b + 0 * HH);
        float xw1 = __ldg(xw_b + 1 * HH);
        float xw2 = __ldg(xw_b + 2 * HH);
        float xw3 = __ldg(xw_b + 3 * HH);

        // Wait for h(t) from all 8 CTAs (buffer t&1); t=0 reads the zeroed buffer.
        if (t > 0) {
            uint32_t mb     = mb_local + (uint32_t)((t & 1) * 8);
            uint32_t parity = (uint32_t)(((t >> 1) ^ t ^ 1) & 1);
            mbar_wait_cluster(mb, parity);
        }

        // ---- GEMM partial: z[r][bbase..bbase+8) over k-half ----
        const float* HsR = Hs + (t & 1) * (16 * HS_STRIDE) + bbase * HS_STRIDE + kbase;
        double a0 = 0.0, a1 = 0.0, a2 = 0.0, a3 = 0.0;
        double a4 = 0.0, a5 = 0.0, a6 = 0.0, a7 = 0.0;

        #pragma unroll 1
        for (int k = 0; k < 128; k += 4) {
            double2 w  = *(const double2*)(wrow + k);
            double2 h0 = *(const double2*)(HsR + 0 * HS_STRIDE + k);
            double2 h1 = *(const double2*)(HsR + 1 * HS_STRIDE + k);
            double2 h2 = *(const double2*)(HsR + 2 * HS_STRIDE + k);
            double2 h3 = *(const double2*)(HsR + 3 * HS_STRIDE + k);
            double2 h4 = *(const double2*)(HsR + 4 * HS_STRIDE + k);
            double2 h5 = *(const double2*)(HsR + 5 * HS_STRIDE + k);
            double2 h6 = *(const double2*)(HsR + 6 * HS_STRIDE + k);
            double2 h7 = *(const double2*)(HsR + 7 * HS_STRIDE + k);
            ffma2(a0, w.x, h0.x); ffma2(a0, w.y, h0.y);
            ffma2(a1, w.x, h1.x); ffma2(a1, w.y, h1.y);
            ffma2(a2, w.x, h2.x); ffma2(a2, w.y, h2.y);
            ffma2(a3, w.x, h3.x); ffma2(a3, w.y, h3.y);
            ffma2(a4, w.x, h4.x); ffma2(a4, w.y, h4.y);
            ffma2(a5, w.x, h5.x); ffma2(a5, w.y, h5.y);
            ffma2(a6, w.x, h6.x); ffma2(a6, w.y, h6.y);
            ffma2(a7, w.x, h7.x); ffma2(a7, w.y, h7.y);
        }

        float* zrow = Zs + (kh * 128 + r) * ZS_STRIDE + bbase;
        zrow[0] = dsum(a0); zrow[1] = dsum(a1); zrow[2] = dsum(a2); zrow[3] = dsum(a3);
        zrow[4] = dsum(a4); zrow[5] = dsum(a5); zrow[6] = dsum(a6); zrow[7] = dsum(a7);
        __syncthreads();

        // ---- epilogue: one (batch, j) per thread ----
        const int nb = (t + 1) & 1;
        const int ZH = 128 * ZS_STRIDE;
        const float* z0 = Zs + (0 * 32 + cg) * ZS_STRIDE + bq;
        const float* z1 = Zs + (1 * 32 + cg) * ZS_STRIDE + bq;
        const float* z2 = Zs + (2 * 32 + cg) * ZS_STRIDE + bq;
        const float* z3 = Zs + (3 * 32 + cg) * ZS_STRIDE + bq;

        float zi = z0[0] + z0[ZH] + xw0;
        float zf = z1[0] + z1[ZH] + xw1;
        float zg = z2[0] + z2[ZH] + xw2;
        float zo = z3[0] + z3[ZH] + xw3;

        float ig = sigmoid_mufu(zi);
        float fg = sigmoid_mufu(zf);
        float gg = tanh_mufu(zg);
        float og = sigmoid_mufu(zo);

        float cn = fmaf(fg, creg, ig * gg);
        float hn = og * tanh_mufu(cn);
        creg = cn;

        // Multicast h(t+1) into buffer nb of all 8 cluster CTAs
        uint32_t off = (uint32_t)(((nb * 16 + bq) * HS_STRIDE + jg) * 4);
        #pragma unroll
        for (int p = 0; p < 8; p++)
            asm volatile("st.shared::cluster.f32 [%0], %1;"
                         :: "r"(peer[p] + off), "f"(hn) : "memory");

        if (write_out0)
            g_out0[((size_t)t * BB + (b0 + bq)) * HH + jg] = hn;
        else if (t == TT - 1)
            g_hfin[(b0 + bq) * HH + jg] = hn;

        // Warp-elected arrive on each peer's mbarrier[nb]; __syncwarp orders all
        // lanes' DSMEM stores before lane 0's release-arrive.
        __syncwarp();
        if (cg == 0) {
            uint32_t mo = (uint32_t)(MB_DELTA + nb * 8);
            #pragma unroll
            for (int p = 0; p < 8; p++)
                mbar_arrive_remote(peer[p] + mo);
        }
    }

    // No CTA may exit while peers' final DSMEM stores/arrives are in flight.
    asm volatile("barrier.cluster.arrive.aligned;" ::: "memory");
    asm volatile("barrier.cluster.wait.aligned;"   ::: "memory");
}

// ---------------- final linear: out[b] = dot(h_last[b], Wf) + bf ----------------
__global__ __launch_bounds__(256)
void final_kernel(const float* __restrict__ Wf, const float* __restrict__ bf,
                  float* __restrict__ out)
{
    int warp = (blockIdx.x * blockDim.x + threadIdx.x) >> 5;
    int lane = threadIdx.x & 31;
    if (warp >= BB) return;
    const float* h = g_hfin + warp * HH;
    float s = 0.0f;
    for (int k = lane; k < HH; k += 32) s += h[k] * Wf[k];
    #pragma unroll
    for (int o = 16; o > 0; o >>= 1) s += __shfl_xor_sync(0xffffffffu, s, o);
    if (lane == 0) out[warp] = s + bf[0];
}

// ---------------- launch: 5 graph nodes ----------------
extern "C" void kernel_launch(void* const* d_in, const int* in_sizes, int n_in,
                              void* d_out, int out_size)
{
    const float* x    = (const float*)d_in[0];
    const float* Wih0 = (const float*)d_in[1];
    const float* Whh0 = (const float*)d_in[2];
    const float* bih0 = (const float*)d_in[3];
    const float* bhh0 = (const float*)d_in[4];
    const float* Wih1 = (const float*)d_in[5];
    const float* Whh1 = (const float*)d_in[6];
    const float* bih1 = (const float*)d_in[7];
    const float* bhh1 = (const float*)d_in[8];
    const float* Wf   = (const float*)d_in[9];
    const float* bf   = (const float*)d_in[10];
    float* out = (float*)d_out;

    cudaFuncSetAttribute(lstm_layer_kernel,
                         cudaFuncAttributeMaxDynamicSharedMemorySize,
                         LSTM_SMEM_BYTES);
    cudaFuncSetAttribute(proj_kernel<DD, 0>,
                         cudaFuncAttributeMaxDynamicSharedMemorySize,
                         PROJ_SMEM_BYTES);
    cudaFuncSetAttribute(proj_kernel<HH, 1>,
                         cudaFuncAttributeMaxDynamicSharedMemorySize,
                         PROJ_SMEM_BYTES);

    const dim3 proj_grid(TT * BB / 64, G4H / 128);   // (2048, 8)
    const dim3 lstm_grid(8, 16);                     // 16 clusters of 8 CTAs

    proj_kernel<DD, 0><<<proj_grid, 256, PROJ_SMEM_BYTES>>>(x, Wih0, bih0, bhh0);
    lstm_layer_kernel<<<lstm_grid, 512, LSTM_SMEM_BYTES>>>(Whh0, 1);

    proj_kernel<HH, 1><<<proj_grid, 256, PROJ_SMEM_BYTES>>>(nullptr, Wih1, bih1, bhh1);
    lstm_layer_kernel<<<lstm_grid, 512, LSTM_SMEM_BYTES>>>(Whh1, 0);

    final_kernel<<<(BB * 32 + 255) / 256, 256>>>(Wf, bf, out);
}

// round 14
// speedup vs baseline: 1.2912x; 1.2912x over previous
#include <cuda_runtime.h>
#include <math.h>
#include <stdint.h>

#define BB   256   // batch
#define TT   512   // seq len
#define DD   64    // input size
#define HH   256   // hidden
#define G4H  1024  // 4*H

// ---------------- static device scratch (no runtime allocations) ----------------
__device__ float g_xw[(size_t)TT * BB * G4H];   // input projections (reused per layer)
__device__ float g_out0[(size_t)TT * BB * HH];  // layer-0 outputs
__device__ float g_hfin[BB * HH];               // final hidden state of layer 1

// packed f32x2 FMA (Blackwell FFMA2; PTX-only)
__device__ __forceinline__ void ffma2(double& acc, double a, double b) {
    asm("fma.rn.f32x2 %0, %1, %2, %3;" : "=d"(acc) : "d"(a), "d"(b), "d"(acc));
}
__device__ __forceinline__ float dsum(double d) {
    return __int_as_float(__double2loint(d)) + __int_as_float(__double2hiint(d));
}

// ---------------- input projection GEMM (round-10 validated, f32x2) ----------------
// g_xw[m][n] = sum_k in[m][k] * W[n][k] + b1[n] + b2[n],  m = t*BB + b
template<int K, int SRC>
__global__ __launch_bounds__(256)
void proj_kernel(const float* __restrict__ in,
                 const float* __restrict__ W,
                 const float* __restrict__ b1,
                 const float* __restrict__ b2)
{
    __shared__ __align__(16) float As[32][66];
    __shared__ __align__(16) float Ws[128][66];

    const int m0  = blockIdx.x * 32;
    const int n0  = blockIdx.y * 128;
    const int tid = threadIdx.x;        // 256 threads
    const int nn  = tid & 31;
    const int mg  = tid >> 5;           // 0..7

    double acc[4][4];
    #pragma unroll
    for (int i = 0; i < 4; i++)
        #pragma unroll
        for (int j = 0; j < 4; j++) acc[i][j] = 0.0;

    for (int k0 = 0; k0 < K; k0 += 64) {
        for (int idx = tid; idx < 32 * 32; idx += 256) {
            int r  = idx >> 5;
            int kd = idx & 31;
            int m  = m0 + r;
            const float* src;
            if (SRC == 0) {
                int b = m & (BB - 1);
                int t = m >> 8;
                src = in + (size_t)(b * TT + t) * DD;
            } else {
                src = g_out0 + (size_t)m * K;
            }
            *(float2*)&As[r][kd * 2] = *(const float2*)(src + k0 + kd * 2);
        }
        for (int idx = tid; idx < 128 * 32; idx += 256) {
            int r  = idx >> 5;
            int kd = idx & 31;
            *(float2*)&Ws[r][kd * 2] =
                *(const float2*)(W + (size_t)(n0 + r) * K + k0 + kd * 2);
        }
        __syncthreads();

        #pragma unroll 8
        for (int kk = 0; kk < 32; kk++) {
            double a[4], w[4];
            #pragma unroll
            for (int i = 0; i < 4; i++) a[i] = *(const double*)&As[mg * 4 + i][kk * 2];
            #pragma unroll
            for (int i = 0; i < 4; i++) w[i] = *(const double*)&Ws[nn + 32 * i][kk * 2];
            #pragma unroll
            for (int i = 0; i < 4; i++)
                #pragma unroll
                for (int j = 0; j < 4; j++)
                    ffma2(acc[i][j], a[i], w[j]);
        }
        __syncthreads();
    }

    #pragma unroll
    for (int i = 0; i < 4; i++) {
        int m = m0 + mg * 4 + i;
        #pragma unroll
        for (int j = 0; j < 4; j++) {
            int n = n0 + nn + 32 * j;
            g_xw[(size_t)m * G4H + n] = dsum(acc[i][j]) + b1[n] + b2[n];
        }
    }
}

// ---------------- MUFU gates (cost is per-warp-instruction: tiny) ----------------
__device__ __forceinline__ float sigmoid_mufu(float z) {
    return __fdividef(1.0f, 1.0f + __expf(-z));
}
__device__ __forceinline__ float tanh_mufu(float z) {
    return 1.0f - __fdividef(2.0f, __expf(2.0f * z) + 1.0f);
}

// ---------------- persistent cluster LSTM layer: TWO batch streams per CTA -------
// Grid (8, 8): x = j-tile (cluster rank), y = batch-PAIR. 64 CTAs, 256 thr (8 warps).
// Each CTA processes batch-tiles A (=2*bx) and B (=2*bx+1): independent streams that
// share the smem Whh slice; their GEMMs interleave (ILP), the per-step tail
// (barrier + DSMEM drain) is paid once per two tiles.
// GEMM: warp = (bh = w&1, rb = w>>1); thread: 1 row x (8 bA + 8 bB) x full k=256.
// Epilogue: thread = (j = lane, warp -> 2 batches per stream).  c in regs (4/thread).
#define WS_STRIDE 260
#define HS_STRIDE 264
#define ZS_STRIDE 17
#define WS_FLOATS (128 * WS_STRIDE)             // 33280
#define HS_FLOATS (2 * 16 * HS_STRIDE)          // 8448 per stream
#define ZS_FLOATS (128 * ZS_STRIDE)             // 2176 per stream
#define LSTM_SMEM_FLOATS (WS_FLOATS + 2 * HS_FLOATS + 2 * ZS_FLOATS)   // 54528
#define LSTM_SMEM_BYTES  (LSTM_SMEM_FLOATS * 4)                        // 218,112 B

__global__ __cluster_dims__(8, 1, 1) __launch_bounds__(256, 1)
void lstm_layer_kernel(const float* __restrict__ Whh, int write_out0)
{
    extern __shared__ __align__(16) float smem[];
    float* Ws  = smem;                              // [128][WS_STRIDE]
    float* HsA = smem + WS_FLOATS;                  // [2][16][HS_STRIDE]
    float* HsB = HsA + HS_FLOATS;                   // [2][16][HS_STRIDE]
    float* ZsA = HsB + HS_FLOATS;                   // [128][ZS_STRIDE]
    float* ZsB = ZsA + ZS_FLOATS;                   // [128][ZS_STRIDE]

    const int tid  = threadIdx.x;                   // 256 threads
    const int lane = tid & 31;
    const int warp = tid >> 5;                      // 0..7
    // GEMM mapping
    const int bh = warp & 1;                        // batch-half within stream
    const int rb = warp >> 1;                       // row block 0..3
    const int r  = rb * 32 + lane;                  // row = gate*32 + j
    // epilogue mapping
    const int cg = lane;
    const int bq = warp;                            // 2 batches per stream
    const int by = blockIdx.x;                      // cluster rank (j-tile)
    const int bx = blockIdx.y;                      // batch pair
    const int j0 = by * 32;
    const int jg = j0 + cg;
    const int b0A = (2 * bx)     * 16;
    const int b0B = (2 * bx + 1) * 16;

    // Stage Whh slice: smem row c = g*32+jj  <-  Whh row g*HH + j0 + jj
    for (int idx = tid; idx < 128 * 64; idx += 256) {
        int c   = idx >> 6;
        int kq  = idx & 63;
        int row = (c >> 5) * HH + j0 + (c & 31);
        float4 v = *(const float4*)(Whh + (size_t)row * HH + kq * 4);
        *(float4*)(Ws + c * WS_STRIDE + kq * 4) = v;
    }
    // Zero h buffers 0 (step 0 reads them; step-0 h goes to buffer 1)
    for (int idx = tid; idx < 16 * HS_STRIDE; idx += 256) {
        HsA[idx] = 0.0f;
        HsB[idx] = 0.0f;
    }
    __syncthreads();

    // Remote HsA base addresses for all 8 cluster ranks (HsB = +HS_FLOATS*4 bytes)
    uint32_t hsA_local;
    asm("{ .reg .u64 t; cvta.to.shared.u64 t, %1; cvt.u32.u64 %0, t; }"
        : "=r"(hsA_local) : "l"(HsA));
    uint32_t peer[8];
    #pragma unroll
    for (int p = 0; p < 8; p++)
        asm("mapa.shared::cluster.u32 %0, %1, %2;"
            : "=r"(peer[p]) : "r"(hsA_local), "r"(p));
    const uint32_t HSB_OFF = (uint32_t)(HS_FLOATS * 4);

    float cA[2] = {0.0f, 0.0f};                     // c for stream A: (b0A+bq*2+bi, jg)
    float cB[2] = {0.0f, 0.0f};

    asm volatile("barrier.cluster.arrive.aligned;" ::: "memory");
    asm volatile("barrier.cluster.wait.aligned;"   ::: "memory");

    const float* wrow = Ws + r * WS_STRIDE;

    for (int t = 0; t < TT; t++) {
        // Prefetch xw for both streams' epilogues (independent of h)
        float xwA[2][4], xwB[2][4];
        #pragma unroll
        for (int bi = 0; bi < 2; bi++) {
            const float* pa = g_xw + ((size_t)t * BB + (b0A + bq * 2 + bi)) * G4H + jg;
            const float* pb = g_xw + ((size_t)t * BB + (b0B + bq * 2 + bi)) * G4H + jg;
            #pragma unroll
            for (int g = 0; g < 4; g++) {
                xwA[bi][g] = __ldg(pa + g * HH);
                xwB[bi][g] = __ldg(pb + g * HH);
            }
        }

        // ---- interleaved GEMM for both streams ----
        const float* HA = HsA + (t & 1) * (16 * HS_STRIDE) + (bh * 8) * HS_STRIDE;
        const float* HB = HsB + (t & 1) * (16 * HS_STRIDE) + (bh * 8) * HS_STRIDE;
        double accA[8], accB[8];
        #pragma unroll
        for (int b = 0; b < 8; b++) { accA[b] = 0.0; accB[b] = 0.0; }

        #pragma unroll 2
        for (int k = 0; k < HH; k += 4) {
            double2 w = *(const double2*)(wrow + k);
            #pragma unroll
            for (int b = 0; b < 8; b++) {
                double2 ha = *(const double2*)(HA + b * HS_STRIDE + k);
                ffma2(accA[b], w.x, ha.x);
                ffma2(accA[b], w.y, ha.y);
            }
            #pragma unroll
            for (int b = 0; b < 8; b++) {
                double2 hb = *(const double2*)(HB + b * HS_STRIDE + k);
                ffma2(accB[b], w.x, hb.x);
                ffma2(accB[b], w.y, hb.y);
            }
        }

        float* zra = ZsA + r * ZS_STRIDE + bh * 8;
        float* zrb = ZsB + r * ZS_STRIDE + bh * 8;
        #pragma unroll
        for (int b = 0; b < 8; b++) { zra[b] = dsum(accA[b]); zrb[b] = dsum(accB[b]); }
        __syncthreads();

        // ---- epilogue: 2 batches x 2 streams per thread ----
        const int nb = (t + 1) & 1;
        #pragma unroll
        for (int bi = 0; bi < 2; bi++) {
            const int bl = bq * 2 + bi;
            // stream A
            {
                float zi = ZsA[(0 * 32 + cg) * ZS_STRIDE + bl] + xwA[bi][0];
                float zf = ZsA[(1 * 32 + cg) * ZS_STRIDE + bl] + xwA[bi][1];
                float zg = ZsA[(2 * 32 + cg) * ZS_STRIDE + bl] + xwA[bi][2];
                float zo = ZsA[(3 * 32 + cg) * ZS_STRIDE + bl] + xwA[bi][3];
                float ig = sigmoid_mufu(zi);
                float fg = sigmoid_mufu(zf);
                float gg = tanh_mufu(zg);
                float og = sigmoid_mufu(zo);
                float cn = fmaf(fg, cA[bi], ig * gg);
                float hn = og * tanh_mufu(cn);
                cA[bi] = cn;
                uint32_t off = (uint32_t)(((nb * 16 + bl) * HS_STRIDE + jg) * 4);
                #pragma unroll
                for (int p = 0; p < 8; p++)
                    asm volatile("st.shared::cluster.f32 [%0], %1;"
                                 :: "r"(peer[p] + off), "f"(hn) : "memory");
                if (write_out0)
                    g_out0[((size_t)t * BB + (b0A + bl)) * HH + jg] = hn;
                else if (t == TT - 1)
                    g_hfin[(b0A + bl) * HH + jg] = hn;
            }
            // stream B
            {
                float zi = ZsB[(0 * 32 + cg) * ZS_STRIDE + bl] + xwB[bi][0];
                float zf = ZsB[(1 * 32 + cg) * ZS_STRIDE + bl] + xwB[bi][1];
                float zg = ZsB[(2 * 32 + cg) * ZS_STRIDE + bl] + xwB[bi][2];
                float zo = ZsB[(3 * 32 + cg) * ZS_STRIDE + bl] + xwB[bi][3];
                float ig = sigmoid_mufu(zi);
                float fg = sigmoid_mufu(zf);
                float gg = tanh_mufu(zg);
                float og = sigmoid_mufu(zo);
                float cn = fmaf(fg, cB[bi], ig * gg);
                float hn = og * tanh_mufu(cn);
                cB[bi] = cn;
                uint32_t off = (uint32_t)(((nb * 16 + bl) * HS_STRIDE + jg) * 4) + HSB_OFF;
                #pragma unroll
                for (int p = 0; p < 8; p++)
                    asm volatile("st.shared::cluster.f32 [%0], %1;"
                                 :: "r"(peer[p] + off), "f"(hn) : "memory");
                if (write_out0)
                    g_out0[((size_t)t * BB + (b0B + bl)) * HH + jg] = hn;
                else if (t == TT - 1)
                    g_hfin[(b0B + bl) * HH + jg] = hn;
            }
        }

        // Release our DSMEM stores early; overlap barrier latency with nothing
        // dependent, then acquire peers' stores.
        asm volatile("barrier.cluster.arrive.aligned;" ::: "memory");
        asm volatile("barrier.cluster.wait.aligned;"   ::: "memory");
    }
}

// ---------------- final linear: out[b] = dot(h_last[b], Wf) + bf ----------------
__global__ __launch_bounds__(256)
void final_kernel(const float* __restrict__ Wf, const float* __restrict__ bf,
                  float* __restrict__ out)
{
    int warp = (blockIdx.x * blockDim.x + threadIdx.x) >> 5;
    int lane = threadIdx.x & 31;
    if (warp >= BB) return;
    const float* h = g_hfin + warp * HH;
    float s = 0.0f;
    for (int k = lane; k < HH; k += 32) s += h[k] * Wf[k];
    #pragma unroll
    for (int o = 16; o > 0; o >>= 1) s += __shfl_xor_sync(0xffffffffu, s, o);
    if (lane == 0) out[warp] = s + bf[0];
}

// ---------------- launch: 5 graph nodes ----------------
extern "C" void kernel_launch(void* const* d_in, const int* in_sizes, int n_in,
                              void* d_out, int out_size)
{
    const float* x    = (const float*)d_in[0];
    const float* Wih0 = (const float*)d_in[1];
    const float* Whh0 = (const float*)d_in[2];
    const float* bih0 = (const float*)d_in[3];
    const float* bhh0 = (const float*)d_in[4];
    const float* Wih1 = (const float*)d_in[5];
    const float* Whh1 = (const float*)d_in[6];
    const float* bih1 = (const float*)d_in[7];
    const float* bhh1 = (const float*)d_in[8];
    const float* Wf   = (const float*)d_in[9];
    const float* bf   = (const float*)d_in[10];
    float* out = (float*)d_out;

    cudaFuncSetAttribute(lstm_layer_kernel,
                         cudaFuncAttributeMaxDynamicSharedMemorySize,
                         LSTM_SMEM_BYTES);

    const dim3 proj_grid(TT * BB / 32, G4H / 128);   // (4096, 8)
    const dim3 lstm_grid(8, 8);                      // 8 clusters of 8 CTAs (2 streams each)

    proj_kernel<DD, 0><<<proj_grid, 256>>>(x, Wih0, bih0, bhh0);
    lstm_layer_kernel<<<lstm_grid, 256, LSTM_SMEM_BYTES>>>(Whh0, 1);

    proj_kernel<HH, 1><<<proj_grid, 256>>>(nullptr, Wih1, bih1, bhh1);
    lstm_layer_kernel<<<lstm_grid, 256, LSTM_SMEM_BYTES>>>(Whh1, 0);

    final_kernel<<<(BB * 32 + 255) / 256, 256>>>(Wf, bf, out);
}

// round 17
// speedup vs baseline: 2.6735x; 2.0707x over previous
#include <cuda_runtime.h>
#include <cuda_bf16.h>
#include <math.h>
#include <stdint.h>

#define BB   256   // batch
#define TT   512   // seq len
#define DD   64    // input size
#define HH   256   // hidden
#define G4H  1024  // 4*H

// ---------------- static device scratch (no runtime allocations) ----------------
__device__ float g_xw[(size_t)TT * BB * G4H];   // input projections (reused per layer)
__device__ float g_out0[(size_t)TT * BB * HH];  // layer-0 outputs
__device__ float g_hfin[BB * HH];               // final hidden state of layer 1

// packed f32x2 FMA (Blackwell FFMA2; PTX-only)
__device__ __forceinline__ void ffma2(double& acc, double a, double b) {
    asm("fma.rn.f32x2 %0, %1, %2, %3;" : "=d"(acc) : "d"(a), "d"(b), "d"(acc));
}
__device__ __forceinline__ float dsum(double d) {
    return __int_as_float(__double2loint(d)) + __int_as_float(__double2hiint(d));
}

// ---------------- input projection GEMM (validated rounds 10-14) ----------------
template<int K, int SRC>
__global__ __launch_bounds__(256)
void proj_kernel(const float* __restrict__ in,
                 const float* __restrict__ W,
                 const float* __restrict__ b1,
                 const float* __restrict__ b2)
{
    __shared__ __align__(16) float As[32][66];
    __shared__ __align__(16) float Ws[128][66];

    const int m0  = blockIdx.x * 32;
    const int n0  = blockIdx.y * 128;
    const int tid = threadIdx.x;
    const int nn  = tid & 31;
    const int mg  = tid >> 5;

    double acc[4][4];
    #pragma unroll
    for (int i = 0; i < 4; i++)
        #pragma unroll
        for (int j = 0; j < 4; j++) acc[i][j] = 0.0;

    for (int k0 = 0; k0 < K; k0 += 64) {
        for (int idx = tid; idx < 32 * 32; idx += 256) {
            int r  = idx >> 5;
            int kd = idx & 31;
            int m  = m0 + r;
            const float* src;
            if (SRC == 0) {
                int b = m & (BB - 1);
                int t = m >> 8;
                src = in + (size_t)(b * TT + t) * DD;
            } else {
                src = g_out0 + (size_t)m * K;
            }
            *(float2*)&As[r][kd * 2] = *(const float2*)(src + k0 + kd * 2);
        }
        for (int idx = tid; idx < 128 * 32; idx += 256) {
            int r  = idx >> 5;
            int kd = idx & 31;
            *(float2*)&Ws[r][kd * 2] =
                *(const float2*)(W + (size_t)(n0 + r) * K + k0 + kd * 2);
        }
        __syncthreads();

        #pragma unroll 8
        for (int kk = 0; kk < 32; kk++) {
            double a[4], w[4];
            #pragma unroll
            for (int i = 0; i < 4; i++) a[i] = *(const double*)&As[mg * 4 + i][kk * 2];
            #pragma unroll
            for (int i = 0; i < 4; i++) w[i] = *(const double*)&Ws[nn + 32 * i][kk * 2];
            #pragma unroll
            for (int i = 0; i < 4; i++)
                #pragma unroll
                for (int j = 0; j < 4; j++)
                    ffma2(acc[i][j], a[i], w[j]);
        }
        __syncthreads();
    }

    #pragma unroll
    for (int i = 0; i < 4; i++) {
        int m = m0 + mg * 4 + i;
        #pragma unroll
        for (int j = 0; j < 4; j++) {
            int n = n0 + nn + 32 * j;
            g_xw[(size_t)m * G4H + n] = dsum(acc[i][j]) + b1[n] + b2[n];
        }
    }
}

// ---------------- MUFU gates ----------------
__device__ __forceinline__ float sigmoid_mufu(float z) {
    return __fdividef(1.0f, 1.0f + __expf(-z));
}
__device__ __forceinline__ float tanh_mufu(float z) {
    return 1.0f - __fdividef(2.0f, __expf(2.0f * z) + 1.0f);
}

// ---------------- mma.sync m16n8k16 bf16 (base ISA, compiles on sm_103) --------
__device__ __forceinline__ void mma16816(float& d0, float& d1, float& d2, float& d3,
                                         uint32_t a0, uint32_t a1, uint32_t a2, uint32_t a3,
                                         uint32_t b0, uint32_t b1)
{
    asm volatile(
        "mma.sync.aligned.m16n8k16.row.col.f32.bf16.bf16.f32 "
        "{%0,%1,%2,%3}, {%4,%5,%6,%7}, {%8,%9}, {%0,%1,%2,%3};"
        : "+f"(d0), "+f"(d1), "+f"(d2), "+f"(d3)
        : "r"(a0), "r"(a1), "r"(a2), "r"(a3), "r"(b0), "r"(b1));
}

__device__ __forceinline__ uint32_t pack_hi(float2 v, uint32_t& lo) {
    __nv_bfloat16 h0 = __float2bfloat16(v.x);
    __nv_bfloat16 h1 = __float2bfloat16(v.y);
    __nv_bfloat16 l0 = __float2bfloat16(v.x - __bfloat162float(h0));
    __nv_bfloat16 l1 = __float2bfloat16(v.y - __bfloat162float(h1));
    lo = (uint32_t)__bfloat16_as_ushort(l0) | ((uint32_t)__bfloat16_as_ushort(l1) << 16);
    return (uint32_t)__bfloat16_as_ushort(h0) | ((uint32_t)__bfloat16_as_ushort(h1) << 16);
}

// ---------------- persistent cluster LSTM layer — mma.sync recurrence ------------
// Grid (8, 8), cluster 8 (x = j-tile rank), 256 threads (8 warps), 32 batches/CTA.
// z[128r x 32b] = Whh_s[128 x 256] . h[32 x 256]^T  via bf16x3 (AhBh + AhBl + AlBh).
// Warp w: m-tile rows w*16..w*16+15, all 4 n-tiles, K=256 (16 k-steps).
// A-hi: registers (staged once).  A-lo: pre-packed smem fragments (LDS.128/kstep).
// B = h bf16: [b][k] rows, stride 264 bf16 (132 u32 == 4 mod 32 -> conflict-free
// fragment loads), 4 planes [parity][hi|lo], written remotely by the epilogue.
// B-plane bytes:  plane = 32 * 528 = 16896;  parity block = 33792; total 67584 B.
#define BPLANE_B   16896
#define BPAR_B     33792
#define BROW_U32   132                          // 528 B / 4
#define ALO_OFF_F  16896                        // floats (== 67584 B)
#define ZS_OFF_F   (ALO_OFF_F + 16384)          // 33280
#define ZS_STRIDE  33
#define LSTM_SMEM_BYTES ((ZS_OFF_F + 128 * ZS_STRIDE) * 4 + 16)   // ~150 KB

__global__ __cluster_dims__(8, 1, 1) __launch_bounds__(256, 1)
void lstm_layer_kernel(const float* __restrict__ Whh, int write_out0)
{
    extern __shared__ __align__(16) float smem[];
    uint4* Alo = (uint4*)(smem + ALO_OFF_F);    // [128 (w*16+s)][32 lanes] uint4
    float* Zs  = smem + ZS_OFF_F;               // [128][ZS_STRIDE]

    const int tid  = threadIdx.x;
    const int lane = tid & 31;
    const int warp = tid >> 5;                  // 0..7
    const int g    = lane >> 2;                 // fragment groupID
    const int tg   = lane & 3;                  // threadID_in_group
    const int by   = blockIdx.x;                // cluster rank = j-tile
    const int bx   = blockIdx.y;                // batch tile of 32
    const int j0   = by * 32;
    const int b0   = bx * 32;
    const int jj   = lane;                      // epilogue j within tile
    const int jg   = j0 + jj;
    const int bg   = warp;                      // epilogue: batches bg*4..bg*4+3

    uint32_t smem_base;
    asm("{ .reg .u64 t; cvta.to.shared.u64 t, %1; cvt.u32.u64 %0, t; }"
        : "=r"(smem_base) : "l"(smem));

    // ---- zero all B planes (h(0) = 0; step 0 reads parity 0) ----
    for (int i = tid; i < BPAR_B / 2; i += 256)  // 2*BPAR_B bytes / 4 = BPAR_B/2 floats
        smem[i] = 0.0f;

    // ---- stage A: Whh slice as m16n8k16 fragments; hi -> regs, lo -> smem ----
    // rows r0 = w*16+g, r1 = r0+8;  Whh_s[r][k] = Whh[(r>>5)*HH + j0 + (r&31)][k]
    uint32_t Ah[16][4];
    {
        const int r0 = warp * 16 + g;
        const int r1 = r0 + 8;
        const float* W0 = Whh + (size_t)((r0 >> 5) * HH + j0 + (r0 & 31)) * HH;
        const float* W1 = Whh + (size_t)((r1 >> 5) * HH + j0 + (r1 & 31)) * HH;
        #pragma unroll
        for (int s = 0; s < 16; s++) {
            int k0 = s * 16 + 2 * tg;
            uint32_t l0, l1, l2, l3;
            Ah[s][0] = pack_hi(*(const float2*)(W0 + k0),     l0);
            Ah[s][1] = pack_hi(*(const float2*)(W1 + k0),     l1);
            Ah[s][2] = pack_hi(*(const float2*)(W0 + k0 + 8), l2);
            Ah[s][3] = pack_hi(*(const float2*)(W1 + k0 + 8), l3);
            Alo[(warp * 16 + s) * 32 + lane] = make_uint4(l0, l1, l2, l3);
        }
    }
    __syncthreads();

    // remote smem bases for all 8 cluster ranks
    uint32_t peer[8];
    #pragma unroll
    for (int p = 0; p < 8; p++)
        asm("mapa.shared::cluster.u32 %0, %1, %2;" : "=r"(peer[p]) : "r"(smem_base), "r"(p));

    float creg[4] = {0.0f, 0.0f, 0.0f, 0.0f};

    asm volatile("barrier.cluster.arrive.aligned;" ::: "memory");
    asm volatile("barrier.cluster.wait.aligned;"   ::: "memory");

    for (int t = 0; t < TT; t++) {
        // prefetch xw for this thread's 4 (batch, j) epilogue items
        float xw[4][4];
        #pragma unroll
        for (int i = 0; i < 4; i++) {
            const float* p = g_xw + ((size_t)t * BB + (b0 + bg * 4 + i)) * G4H + jg;
            #pragma unroll
            for (int gg2 = 0; gg2 < 4; gg2++) xw[i][gg2] = __ldg(p + gg2 * HH);
        }

        // ---- GEMM: 16 k-steps x 4 n-tiles x 3 bf16 passes ----
        const uint32_t* Bh = (const uint32_t*)smem + (t & 1) * (BPAR_B / 4);
        const uint32_t* Bl = Bh + (BPLANE_B / 4);
        float D[4][4];
        #pragma unroll
        for (int nt = 0; nt < 4; nt++)
            #pragma unroll
            for (int q = 0; q < 4; q++) D[nt][q] = 0.0f;

        #pragma unroll
        for (int s = 0; s < 16; s++) {
            uint4 alv = Alo[(warp * 16 + s) * 32 + lane];
            uint32_t al[4] = {alv.x, alv.y, alv.z, alv.w};
            int kw = s * 8 + tg;
            #pragma unroll
            for (int nt = 0; nt < 4; nt++) {
                int brow = (nt * 8 + g) * BROW_U32;
                uint32_t bh0 = Bh[brow + kw], bh1 = Bh[brow + kw + 4];
                uint32_t bl0 = Bl[brow + kw], bl1 = Bl[brow + kw + 4];
                mma16816(D[nt][0], D[nt][1], D[nt][2], D[nt][3],
                         Ah[s][0], Ah[s][1], Ah[s][2], Ah[s][3], bh0, bh1);
                mma16816(D[nt][0], D[nt][1], D[nt][2], D[nt][3],
                         Ah[s][0], Ah[s][1], Ah[s][2], Ah[s][3], bl0, bl1);
                mma16816(D[nt][0], D[nt][1], D[nt][2], D[nt][3],
                         al[0], al[1], al[2], al[3], bh0, bh1);
            }
        }

        // scatter D to Zs: rows w*16+g (+8), cols nt*8+2tg (+1)
        {
            int r0 = warp * 16 + g;
            #pragma unroll
            for (int nt = 0; nt < 4; nt++) {
                int c = nt * 8 + 2 * tg;
                Zs[r0 * ZS_STRIDE + c]           = D[nt][0];
                Zs[r0 * ZS_STRIDE + c + 1]       = D[nt][1];
                Zs[(r0 + 8) * ZS_STRIDE + c]     = D[nt][2];
                Zs[(r0 + 8) * ZS_STRIDE + c + 1] = D[nt][3];
            }
        }
        __syncthreads();

        // ---- epilogue: 4 (batch, j) per thread ----
        const int nb = (t + 1) & 1;
        const uint32_t nbB = (uint32_t)(nb * BPAR_B);
        #pragma unroll
        for (int i = 0; i < 4; i++) {
            int b = bg * 4 + i;
            float zi = Zs[(0 * 32 + jj) * ZS_STRIDE + b] + xw[i][0];
            float zf = Zs[(1 * 32 + jj) * ZS_STRIDE + b] + xw[i][1];
            float zg = Zs[(2 * 32 + jj) * ZS_STRIDE + b] + xw[i][2];
            float zo = Zs[(3 * 32 + jj) * ZS_STRIDE + b] + xw[i][3];

            float ig = sigmoid_mufu(zi);
            float fg = sigmoid_mufu(zf);
            float gg = tanh_mufu(zg);
            float og = sigmoid_mufu(zo);

            float cn = fmaf(fg, creg[i], ig * gg);
            float hn = og * tanh_mufu(cn);
            creg[i] = cn;

            __nv_bfloat16 hh = __float2bfloat16(hn);
            __nv_bfloat16 hl = __float2bfloat16(hn - __bfloat162float(hh));
            unsigned short uh = __bfloat16_as_ushort(hh);
            unsigned short ul = __bfloat16_as_ushort(hl);
            uint32_t off = nbB + (uint32_t)(b * 528 + jg * 2);
            #pragma unroll
            for (int p = 0; p < 8; p++) {
                asm volatile("st.shared::cluster.u16 [%0], %1;"
                             :: "r"(peer[p] + off), "h"(uh) : "memory");
                asm volatile("st.shared::cluster.u16 [%0], %1;"
                             :: "r"(peer[p] + off + BPLANE_B), "h"(ul) : "memory");
            }

            if (write_out0)
                g_out0[((size_t)t * BB + (b0 + b)) * HH + jg] = hn;
            else if (t == TT - 1)
                g_hfin[(b0 + b) * HH + jg] = hn;
        }

        // orders DSMEM h-writes (and Zs reuse) before the next step
        asm volatile("barrier.cluster.arrive.aligned;" ::: "memory");
        asm volatile("barrier.cluster.wait.aligned;"   ::: "memory");
    }

    asm volatile("barrier.cluster.arrive.aligned;" ::: "memory");
    asm volatile("barrier.cluster.wait.aligned;"   ::: "memory");
}

// ---------------- final linear ----------------
__global__ __launch_bounds__(256)
void final_kernel(const float* __restrict__ Wf, const float* __restrict__ bf,
                  float* __restrict__ out)
{
    int warp = (blockIdx.x * blockDim.x + threadIdx.x) >> 5;
    int lane = threadIdx.x & 31;
    if (warp >= BB) return;
    const float* h = g_hfin + warp * HH;
    float s = 0.0f;
    for (int k = lane; k < HH; k += 32) s += h[k] * Wf[k];
    #pragma unroll
    for (int o = 16; o > 0; o >>= 1) s += __shfl_xor_sync(0xffffffffu, s, o);
    if (lane == 0) out[warp] = s + bf[0];
}

// ---------------- launch: 5 graph nodes ----------------
extern "C" void kernel_launch(void* const* d_in, const int* in_sizes, int n_in,
                              void* d_out, int out_size)
{
    const float* x    = (const float*)d_in[0];
    const float* Wih0 = (const float*)d_in[1];
    const float* Whh0 = (const float*)d_in[2];
    const float* bih0 = (const float*)d_in[3];
    const float* bhh0 = (const float*)d_in[4];
    const float* Wih1 = (const float*)d_in[5];
    const float* Whh1 = (const float*)d_in[6];
    const float* bih1 = (const float*)d_in[7];
    const float* bhh1 = (const float*)d_in[8];
    const float* Wf   = (const float*)d_in[9];
    const float* bf   = (const float*)d_in[10];
    float* out = (float*)d_out;

    cudaFuncSetAttribute(lstm_layer_kernel,
                         cudaFuncAttributeMaxDynamicSharedMemorySize,
                         LSTM_SMEM_BYTES);

    const dim3 proj_grid(TT * BB / 32, G4H / 128);   // (4096, 8)
    const dim3 lstm_grid(8, 8);                      // 8 clusters of 8 CTAs, 32 b each

    proj_kernel<DD, 0><<<proj_grid, 256>>>(x, Wih0, bih0, bhh0);
    lstm_layer_kernel<<<lstm_grid, 256, LSTM_SMEM_BYTES>>>(Whh0, 1);

    proj_kernel<HH, 1><<<proj_grid, 256>>>(nullptr, Wih1, bih1, bhh1);
    lstm_layer_kernel<<<lstm_grid, 256, LSTM_SMEM_BYTES>>>(Whh1, 0);

    final_kernel<<<(BB * 32 + 255) / 256, 256>>>(Wf, bf, out);
}